// round 10
// baseline (speedup 1.0000x reference)
#include <cuda_runtime.h>
#include <cuda_bf16.h>
#include <cstdint>

#define BTOT 16384
#define PFULL 4416          // 64 z + 256 feat + 4096 zz (full)
#define PW2   2624          // 64 z + 256 feat + 2304 zz (8-aligned tri groups)
#define NGRP  288
#define NCH   41            // PW2 / 64
#define SQRTK 11.313708498984761f

__device__ float g_Wpart[4][64 * PFULL];
__device__ __align__(16) __nv_bfloat16 g_Wh[64 * PW2];
__device__ __align__(16) __nv_bfloat16 g_Wl[64 * PW2];
__device__ float g_csq[64];
__device__ float g_bsum[64];
__device__ uchar2 g_gij[NGRP];

// -------- prep stage 1: fold over K (split-k, 4 partials) --------------------
__global__ void prep_fold1(const float* __restrict__ qzw,
                           const float* __restrict__ qfw,
                           const float* __restrict__ qg,
                           const float* __restrict__ cq) {
  __shared__ float cq_s[64 * 32];
  const int tid = threadIdx.x;
  const int kbase = blockIdx.y * 32;
  for (int i = tid; i < 512; i += 256) {
    int row = i >> 3, q = i & 7;
    *(float4*)(cq_s + row * 32 + q * 4) =
        *(const float4*)(cq + row * 128 + kbase + q * 4);
  }
  __syncthreads();

  const int p  = blockIdx.x * 32 + (tid & 7) * 4;
  const int ng = tid >> 3;            // 32 groups x 2 charts
  const float* src; int stride, off;
  if (p < 64)       { src = qzw; stride = 64;   off = p; }
  else if (p < 320) { src = qfw; stride = 256;  off = p - 64; }
  else              { src = qg;  stride = 4096; off = p - 320; }
  src += (size_t)kbase * stride;

  float acc[2][4] = {};
  for (int k0 = 0; k0 < 32; k0 += 8) {
    float4 wv[8];
#pragma unroll
    for (int kk = 0; kk < 8; ++kk)
      wv[kk] = *(const float4*)(src + (size_t)(k0 + kk) * stride + off);
#pragma unroll
    for (int kk = 0; kk < 8; ++kk) {
#pragma unroll
      for (int j = 0; j < 2; ++j) {
        float cv = cq_s[(ng * 2 + j) * 32 + k0 + kk];
        acc[j][0] = fmaf(cv, wv[kk].x, acc[j][0]);
        acc[j][1] = fmaf(cv, wv[kk].y, acc[j][1]);
        acc[j][2] = fmaf(cv, wv[kk].z, acc[j][2]);
        acc[j][3] = fmaf(cv, wv[kk].w, acc[j][3]);
      }
    }
  }
#pragma unroll
  for (int j = 0; j < 2; ++j)
    *(float4*)(g_Wpart[blockIdx.y] + (size_t)(ng * 2 + j) * PFULL + p) =
        *(float4*)acc[j];
}

// ------- prep stage 2: sum partials, tri-fold, hi/lo split, tables ----------
__global__ void prep_fold2() {
  const int tid = threadIdx.x;
  const int pl = blockIdx.x * 64 + (tid & 63);
  const int ng = tid >> 6;                 // 4 groups x 16 charts
  int srcp = -1, srcq = -1;
  if (pl < 320) {
    srcp = pl;
  } else {
    int t = pl - 320;
    int g = t >> 3, w8 = t & 7;
    int i = 0, cum = 0;
    for (int ii = 0; ii < 64; ++ii) {
      int cnt = 8 - (ii >> 3);
      if (g < cum + cnt) { i = ii; break; }
      cum += cnt;
    }
    int b = (i >> 3) + (g - cum);
    int j = b * 8 + w8;
    if (ng == 0 && w8 == 0)
      g_gij[g] = make_uchar2((unsigned char)i, (unsigned char)(b * 8));
    if (j >= i) {
      srcp = 320 + i * 64 + j;
      srcq = (j > i) ? (320 + j * 64 + i) : -1;
    }
  }
#pragma unroll 4
  for (int jj = 0; jj < 16; ++jj) {
    int n = ng * 16 + jj;
    float v = 0.f;
    if (srcp >= 0) {
#pragma unroll
      for (int s = 0; s < 4; ++s) v += g_Wpart[s][(size_t)n * PFULL + srcp];
      if (srcq >= 0)
#pragma unroll
        for (int s = 0; s < 4; ++s) v += g_Wpart[s][(size_t)n * PFULL + srcq];
    }
    __nv_bfloat16 h = __float2bfloat16(v);
    g_Wh[(size_t)n * PW2 + pl] = h;
    g_Wl[(size_t)n * PW2 + pl] = __float2bfloat16(v - __bfloat162float(h));
  }
}

__global__ void prep_small(const float* __restrict__ cq,
                           const float* __restrict__ qzb,
                           const float* __restrict__ qfb) {
  int n = threadIdx.x;
  if (n >= 64) return;
  const float* r = cq + n * 128;
  float cs = 0.f, bs = 0.f;
  for (int d = 0; d < 64; ++d) cs = fmaf(r[d], r[d], cs);
  for (int k = 0; k < 128; ++k) bs = fmaf(r[k], qzb[k] + qfb[k], bs);
  g_csq[n] = cs;
  g_bsum[n] = bs;
}

// --------------------------- main kernel ------------------------------------
// 128 rows/CTA, grid 128, 1 CTA/SM, homogeneous warps, (4m,2n) warp grid.
#define O_GIJ  0             // uchar2[288] = 576
#define O_ZSQ  576           // float[128]
#define O_CSQ  1088          // float[64]
#define O_BSM  1344          // float[64]
#define O_RMX  1600          // float[128]
#define O_RIV  2112          // float[128]
#define O_ZS   2624          // float[128][68] = 34816
#define O_CT   37440         // float[64][64]  = 16384 (transposed centers)
#define O_XH   53824         // bf16 [2][128][72] = 36864 (Sc overlaps)
#define O_XL   90688         // bf16 [2][128][72] = 36864 (zcS overlaps)
#define O_WH   127552        // bf16 [2][64][72]  = 18432
#define O_WL   145984        // bf16 [2][64][72]  = 18432
#define SMEMB  164416

__device__ __forceinline__ void mma16816(float* c, const uint32_t* a,
                                         const uint32_t* b) {
  asm volatile(
      "mma.sync.aligned.m16n8k16.row.col.f32.bf16.bf16.f32 "
      "{%0,%1,%2,%3},{%4,%5,%6,%7},{%8,%9},{%0,%1,%2,%3};"
      : "+f"(c[0]), "+f"(c[1]), "+f"(c[2]), "+f"(c[3])
      : "r"(a[0]), "r"(a[1]), "r"(a[2]), "r"(a[3]), "r"(b[0]), "r"(b[1]));
}
__device__ __forceinline__ void ldsm4(uint32_t* r, uint32_t saddr) {
  asm volatile(
      "ldmatrix.sync.aligned.m8n8.x4.shared.b16 {%0,%1,%2,%3},[%4];"
      : "=r"(r[0]), "=r"(r[1]), "=r"(r[2]), "=r"(r[3]) : "r"(saddr));
}
#define CP_ASYNC16(dst, src) \
  asm volatile("cp.async.cg.shared.global [%0], [%1], 16;" :: "r"(dst), "l"(src))
#define CP_COMMIT() asm volatile("cp.async.commit_group;" ::: "memory")
#define CP_WAIT0()  asm volatile("cp.async.wait_group 0;" ::: "memory")

__device__ __forceinline__ void split_store(char* xh, char* xl, const float* v) {
  uint32_t ph[4], plo[4];
#pragma unroll
  for (int j = 0; j < 4; ++j) {
    __nv_bfloat162 h2 = __float22bfloat162_rn(make_float2(v[2 * j], v[2 * j + 1]));
    ph[j] = *(uint32_t*)&h2;
    __nv_bfloat162 l2 = __float22bfloat162_rn(
        make_float2(v[2 * j] - __low2float(h2), v[2 * j + 1] - __high2float(h2)));
    plo[j] = *(uint32_t*)&l2;
  }
  *(uint4*)xh = *(uint4*)ph;
  *(uint4*)xl = *(uint4*)plo;
}

__global__ void __launch_bounds__(256)
atlas_main(const float* __restrict__ z, const float* __restrict__ feat,
           const float* __restrict__ cq, float* __restrict__ out,
           int out_size) {
  extern __shared__ char sm[];
  float* zs   = (float*)(sm + O_ZS);    // stride 68
  float* ct   = (float*)(sm + O_CT);    // [d][col], stride 64
  uchar2* gij = (uchar2*)(sm + O_GIJ);
  float* zsq  = (float*)(sm + O_ZSQ);
  float* csqs = (float*)(sm + O_CSQ);
  float* bsm  = (float*)(sm + O_BSM);
  float* rmx  = (float*)(sm + O_RMX);
  float* riv  = (float*)(sm + O_RIV);
  float* Sc   = (float*)(sm + O_XH);    // stride 68, post-loop overlap
  float* zcS  = (float*)(sm + O_XL);    // stride 64, post-loop overlap

  const int tid = threadIdx.x, lane = tid & 31, w = tid >> 5;
  const int gid = lane >> 2, tg = lane & 3;
  const int r0 = blockIdx.x * 128;
  const uint32_t smb = (uint32_t)__cvta_generic_to_shared(sm);

  for (int i = tid; i < 2048; i += 256) {          // z: 128 rows x 16 float4
    int row = i >> 4, q = i & 15;
    *(float4*)(zs + row * 68 + q * 4) =
        ((const float4*)(z + (size_t)(r0 + row) * 64))[q];
  }
  for (int i = tid; i < 4096; i += 256) {          // centers transposed
    int d = i >> 6, n = i & 63;
    ct[d * 64 + n] = cq[n * 128 + d];
  }
  for (int i = tid; i < NGRP; i += 256) gij[i] = g_gij[i];
  if (tid < 64) { csqs[tid] = g_csq[tid]; bsm[tid] = g_bsum[tid]; }
  __syncthreads();

  const int xr = tid >> 1, half = tid & 1;         // X-gen / zc role
  const float* zrow = zs + xr * 68;

  if (tid < 128) {
    float s = 0.f;
    const float* zr = zs + tid * 68;
    for (int d = 0; d < 64; ++d) s = fmaf(zr[d], zr[d], s);
    zsq[tid] = s;
  }

  // prologue: chunk 0 (z region) X-gen + W chunk 0 via cp.async, into buf 0
  {
#pragma unroll
    for (int g = 0; g < 4; ++g) {
      const int j0 = half * 32 + g * 8;
      float v[8];
      float4 u0 = *(const float4*)(zrow + j0);
      float4 u1 = *(const float4*)(zrow + j0 + 4);
      v[0] = u0.x; v[1] = u0.y; v[2] = u0.z; v[3] = u0.w;
      v[4] = u1.x; v[5] = u1.y; v[6] = u1.z; v[7] = u1.w;
      split_store(sm + O_XH + xr * 144 + j0 * 2, sm + O_XL + xr * 144 + j0 * 2, v);
    }
#pragma unroll
    for (int t = 0; t < 4; ++t) {
      int seg = tid * 4 + t;           // 0..1023
      int isLo = seg >> 9, s = seg & 511;
      int n = s >> 3, k8 = s & 7;
      uint32_t dst = smb + (isLo ? O_WL : O_WH) + n * 144 + k8 * 16;
      const char* src = (const char*)(isLo ? g_Wl : g_Wh) +
                        ((size_t)n * PW2) * 2 + k8 * 16;
      CP_ASYNC16(dst, src);
    }
    CP_COMMIT();
    CP_WAIT0();
  }
  __syncthreads();

  const int wm = w >> 1, wn = w & 1;       // 4m x 2n warp grid
  const int m_base = wm * 32, n_base = wn * 32;
  float acc[2][4][4] = {};
  float zc[32];
#pragma unroll
  for (int q = 0; q < 32; ++q) zc[q] = 0.f;

  const uint32_t aoff = ((lane & 15) * 72 + (lane >> 4) * 8) * 2;
  const uint32_t boff =
      (((((lane >> 4) << 3)) + (lane & 7)) * 72 + ((lane >> 3) & 1) * 8) * 2;
  const uint32_t XHb = smb + O_XH + m_base * 144 + aoff;
  const uint32_t XLb = smb + O_XL + m_base * 144 + aoff;
  const uint32_t WHb = smb + O_WH + n_base * 144 + boff;
  const uint32_t WLb = smb + O_WL + n_base * 144 + boff;

  for (int c = 0; c < NCH; ++c) {
    const int cb = c & 1, nb = cb ^ 1, cc = c + 1;
    // kick cp.async W for chunk cc into buf nb (overlaps MMA below)
    if (cc < NCH) {
#pragma unroll
      for (int t = 0; t < 4; ++t) {
        int seg = tid * 4 + t;
        int isLo = seg >> 9, s = seg & 511;
        int n = s >> 3, k8 = s & 7;
        uint32_t dst = smb + (isLo ? O_WL : O_WH) + nb * 9216 + n * 144 + k8 * 16;
        const char* src = (const char*)(isLo ? g_Wl : g_Wh) +
                          ((size_t)n * PW2 + cc * 64) * 2 + k8 * 16;
        CP_ASYNC16(dst, src);
      }
      CP_COMMIT();
    }
    // ---- MMA on buf cb (3-pass split, 64-wide K) ----
    const uint32_t xh0 = XHb + cb * 18432, xl0 = XLb + cb * 18432;
    const uint32_t wh0 = WHb + cb * 9216,  wl0 = WLb + cb * 9216;
#pragma unroll
    for (int kh = 0; kh < 4; ++kh) {
      const uint32_t kb = kh * 32;
      uint32_t bh[8], bl[8];
      ldsm4(bh,     wh0 + kb);
      ldsm4(bh + 4, wh0 + 16 * 144 + kb);
      ldsm4(bl,     wl0 + kb);
      ldsm4(bl + 4, wl0 + 16 * 144 + kb);
#pragma unroll
      for (int mt = 0; mt < 2; ++mt) {
        uint32_t ah[4], al[4];
        ldsm4(ah, xh0 + mt * 2304 + kb);
        ldsm4(al, xl0 + mt * 2304 + kb);
#pragma unroll
        for (int nt = 0; nt < 4; ++nt) {
          mma16816(acc[mt][nt], ah, bh + nt * 2);
          mma16816(acc[mt][nt], ah, bl + nt * 2);
          mma16816(acc[mt][nt], al, bh + nt * 2);
        }
      }
    }
    // ---- produce X chunk cc into buf nb ----
    if (cc < NCH) {
      char* xhd = sm + O_XH + nb * 18432 + xr * 144;
      char* xld = sm + O_XL + nb * 18432 + xr * 144;
#pragma unroll
      for (int g = 0; g < 4; ++g) {
        const int j0 = half * 32 + g * 8;
        float v[8];
        if (cc < 5) {
          const float* fp = feat + (size_t)(r0 + xr) * 256 + (cc * 64 - 64) + j0;
          float4 u0 = *(const float4*)fp;
          float4 u1 = *(const float4*)(fp + 4);
          v[0] = u0.x; v[1] = u0.y; v[2] = u0.z; v[3] = u0.w;
          v[4] = u1.x; v[5] = u1.y; v[6] = u1.z; v[7] = u1.w;
        } else {
          uchar2 ij = gij[(cc - 5) * 8 + half * 4 + g];
          float sc = zrow[ij.x];
          float4 u0 = *(const float4*)(zrow + ij.y);
          float4 u1 = *(const float4*)(zrow + ij.y + 4);
          v[0] = sc * u0.x; v[1] = sc * u0.y; v[2] = sc * u0.z; v[3] = sc * u0.w;
          v[4] = sc * u1.x; v[5] = sc * u1.y; v[6] = sc * u1.z; v[7] = sc * u1.w;
        }
        split_store(xhd + j0 * 2, xld + j0 * 2, v);
      }
    }
    // ---- overlapped fp32 z.c slice (2 dims per chunk, broadcast loads) ----
    if (c < 32) {
      const int d0 = 2 * c;
      const float a0 = zrow[d0], a1 = zrow[d0 + 1];
      const float* ct0 = ct + d0 * 64 + half * 32;
      const float* ct1 = ct0 + 64;
#pragma unroll
      for (int q4 = 0; q4 < 8; ++q4) {
        float4 u = *(const float4*)(ct0 + q4 * 4);
        float4 vv = *(const float4*)(ct1 + q4 * 4);
        zc[q4 * 4 + 0] = fmaf(a0, u.x, fmaf(a1, vv.x, zc[q4 * 4 + 0]));
        zc[q4 * 4 + 1] = fmaf(a0, u.y, fmaf(a1, vv.y, zc[q4 * 4 + 1]));
        zc[q4 * 4 + 2] = fmaf(a0, u.z, fmaf(a1, vv.z, zc[q4 * 4 + 2]));
        zc[q4 * 4 + 3] = fmaf(a0, u.w, fmaf(a1, vv.w, zc[q4 * 4 + 3]));
      }
    }
    if (cc < NCH) CP_WAIT0();
    __syncthreads();
  }

  // ---- dump gem + zc into smem (X buffers dead) ----
#pragma unroll
  for (int mt = 0; mt < 2; ++mt)
#pragma unroll
    for (int nt = 0; nt < 4; ++nt)
#pragma unroll
      for (int q = 0; q < 4; ++q) {
        const int row = m_base + mt * 16 + gid + (q >> 1) * 8;
        const int col = n_base + nt * 8 + tg * 2 + (q & 1);
        Sc[row * 68 + col] = acc[mt][nt][q];
      }
#pragma unroll
  for (int q = 0; q < 32; ++q) zcS[xr * 64 + half * 32 + q] = zc[q];
  __syncthreads();

  // ---- scoring: thread (row, 32 cols) ----
  {
    const float zq = zsq[xr];
    const float tau = fmaxf(SQRTK * fmaxf(1.f - zq, 1e-3f) * 0.5f, 0.01f);
    const float invlam = (1.f - fminf(zq, 0.999f) + 1e-3f) * 0.5f;
    const float dn1 = 1.f - zq;
#pragma unroll 4
    for (int q = 0; q < 32; ++q) {
      const int col = half * 32 + q;
      const float gem = Sc[xr * 68 + col];
      const float cq2 = csqs[col];
      const float dsq = zq + cq2 - 2.f * zcS[xr * 64 + col];
      const float denom = dn1 * (1.f - cq2) + 1e-3f;
      float arg = fmaxf(1.f + 2.f * dsq / denom, 1.001f);
      float dist = logf(arg + sqrtf((arg + 1.f) * (arg - 1.f)));
      Sc[xr * 68 + col] =
          -dist / tau + (gem + bsm[col]) * invlam * (1.f / SQRTK);
    }
  }
  __syncthreads();

  // ---- softmax + argmax ----
  const bool has_k = (out_size >= BTOT * 64 + BTOT);
  if (tid < 128) {
    float m = -1e30f; int am = 0;
    const float* sr = Sc + tid * 68;
    for (int n = 0; n < 64; ++n) {
      float v = sr[n];
      if (v > m) { m = v; am = n; }
    }
    float s = 0.f;
    for (int n = 0; n < 64; ++n) s += __expf(sr[n] - m);
    rmx[tid] = m;
    riv[tid] = 1.f / s;
    if (has_k) out[BTOT * 64 + r0 + tid] = (float)am;
  }
  __syncthreads();
  for (int i = tid; i < 2048; i += 256) {           // 128 rows x 16 float4
    int r = i >> 4, q = i & 15;
    float mv = rmx[r], iv = riv[r];
    const float* sr = Sc + r * 68 + q * 4;
    float4 o;
    o.x = __expf(sr[0] - mv) * iv;
    o.y = __expf(sr[1] - mv) * iv;
    o.z = __expf(sr[2] - mv) * iv;
    o.w = __expf(sr[3] - mv) * iv;
    *(float4*)(out + (size_t)(r0 + r) * 64 + q * 4) = o;
  }
}

// ----------------------------------------------------------------------------
extern "C" void kernel_launch(void* const* d_in, const int* in_sizes, int n_in,
                              void* d_out, int out_size) {
  const float* z    = (const float*)d_in[0];
  const float* feat = (const float*)d_in[1];
  const float* qzw  = (const float*)d_in[2];
  const float* qzb  = (const float*)d_in[3];
  const float* qfw  = (const float*)d_in[4];
  const float* qfb  = (const float*)d_in[5];
  const float* qg   = (const float*)d_in[6];
  const float* cq   = (const float*)d_in[7];
  float* out = (float*)d_out;

  prep_fold1<<<dim3(PFULL / 32, 4), 256>>>(qzw, qfw, qg, cq);
  prep_fold2<<<NCH, 256>>>();
  prep_small<<<1, 64>>>(cq, qzb, qfb);
  cudaFuncSetAttribute(atlas_main, cudaFuncAttributeMaxDynamicSharedMemorySize,
                       SMEMB);
  atlas_main<<<BTOT / 128, 256, SMEMB>>>(z, feat, cq, out, out_size);
}